// round 16
// baseline (speedup 1.0000x reference)
#include <cuda_runtime.h>
#include <cstdint>

// FrozenBNBEmbedding: out[t, d] = code[ weight[input[t], d] ] * absmax[input[t]]
// DIM == BLOCK == 4096 -> absmax index == vocab row index.
//
// Inputs (metadata order):
//   d_in[0] = input  : int32 [4, 2048]       (8192 token ids)
//   d_in[1] = weight : int32 [50400, 4096]   (int8 codes as int32)
//   d_in[2] = absmax : float32 [50400]
//   d_in[3] = code   : float32 [256]
//   d_out   = float32 [4, 2048, 4096]
//
// Round-15: R1 skeleton (best: 38.1us) + ONE change: write-through stores
// (st.global.wt). Unlike evict_first/.cs (priority hints, both proven
// no-ops here), wt changes ALLOCATION: the 134MB/replay output stream
// should pass through L2 without establishing dirty lines, letting the
// ~121MB distinct-row weight set (vs 126MB L2) stay resident across graph
// replays. Current read hit ~47%; target ~85%+ -> ~150MB DRAM traffic.

#define DIM      4096
#define NTOKENS  8192
#define THREADS  256

__device__ __forceinline__ void stg_wt(float4* p, float4 v) {
    asm volatile("st.global.wt.v4.f32 [%0], {%1,%2,%3,%4};"
                 :: "l"(p), "f"(v.x), "f"(v.y), "f"(v.z), "f"(v.w)
                 : "memory");
}

__global__ __launch_bounds__(THREADS)
void bnb_embed_kernel(const int* __restrict__ input,
                      const int* __restrict__ weight,
                      const float* __restrict__ absmax,
                      const float* __restrict__ code,
                      float* __restrict__ out)
{
    __shared__ float s_code[256];
    s_code[threadIdx.x] = code[threadIdx.x];   // THREADS == 256
    __syncthreads();

    const int t   = blockIdx.x;                // token index 0..8191
    const int tok = input[t];                  // vocab row
    const float scale = __ldg(&absmax[tok]);

    const int4* __restrict__ wrow =
        reinterpret_cast<const int4*>(weight + (size_t)tok * DIM);
    float4* __restrict__ orow =
        reinterpret_cast<float4*>(out + (size_t)t * DIM);

    const int i = threadIdx.x;

    // Front-batch all four 16B loads (MLP=4 per thread).
    int4 q0 = wrow[i];
    int4 q1 = wrow[i + 256];
    int4 q2 = wrow[i + 512];
    int4 q3 = wrow[i + 768];

    float4 o;
    o.x = s_code[q0.x & 255] * scale;
    o.y = s_code[q0.y & 255] * scale;
    o.z = s_code[q0.z & 255] * scale;
    o.w = s_code[q0.w & 255] * scale;
    stg_wt(&orow[i], o);

    o.x = s_code[q1.x & 255] * scale;
    o.y = s_code[q1.y & 255] * scale;
    o.z = s_code[q1.z & 255] * scale;
    o.w = s_code[q1.w & 255] * scale;
    stg_wt(&orow[i + 256], o);

    o.x = s_code[q2.x & 255] * scale;
    o.y = s_code[q2.y & 255] * scale;
    o.z = s_code[q2.z & 255] * scale;
    o.w = s_code[q2.w & 255] * scale;
    stg_wt(&orow[i + 512], o);

    o.x = s_code[q3.x & 255] * scale;
    o.y = s_code[q3.y & 255] * scale;
    o.z = s_code[q3.z & 255] * scale;
    o.w = s_code[q3.w & 255] * scale;
    stg_wt(&orow[i + 768], o);
}

extern "C" void kernel_launch(void* const* d_in, const int* in_sizes, int n_in,
                              void* d_out, int out_size)
{
    const int*   input  = (const int*)  d_in[0];
    const int*   weight = (const int*)  d_in[1];
    const float* absmax = (const float*)d_in[2];
    const float* code   = (const float*)d_in[3];
    float*       out    = (float*)d_out;

    bnb_embed_kernel<<<NTOKENS, THREADS>>>(input, weight, absmax, code, out);
}